// round 9
// baseline (speedup 1.0000x reference)
#include <cuda_runtime.h>
#include <cstdint>

// out[N,N] = diag(ics_mask - params * r_mask), N = 12288. Pure store-bound (604 MB).
// R8 experiment: driver cudaMemsetAsync for the bulk zero-fill (known-best fill
// bandwidth reference; capturable as a graph memset node) + a tiny scatter
// kernel for the 12288 diagonal elements. Discriminates "our store path is
// 84%-limited" vs "chip fill ceiling is 84%".

static constexpr unsigned N = 12288u;

__global__ void diag_scatter_kernel(
    float* __restrict__ out,
    const float* __restrict__ params,
    const int*   __restrict__ r_mask,
    const int*   __restrict__ ics_mask)
{
    unsigned i = blockIdx.x * blockDim.x + threadIdx.x;   // < N exactly
    float val = (float)ics_mask[i] - params[i] * (float)r_mask[i];
    out[(size_t)i * (N + 1u)] = val;
}

extern "C" void kernel_launch(void* const* d_in, const int* in_sizes, int n_in,
                              void* d_out, int out_size)
{
    const float* params   = (const float*)d_in[0];
    const int*   r_mask   = (const int*)  d_in[1];
    const int*   ics_mask = (const int*)  d_in[2];
    float*       out      = (float*)d_out;

    (void)in_sizes; (void)n_in; (void)out_size;

    // Bulk zero fill: 603,979,776 bytes. Async memset -> graph memset node.
    cudaMemsetAsync(out, 0, (size_t)N * N * sizeof(float));

    // Diagonal scatter: 12288 elements, stream-ordered after the memset.
    diag_scatter_kernel<<<N / 256u, 256u>>>(out, params, r_mask, ics_mask);
}

// round 10
// speedup vs baseline: 1.0512x; 1.0512x over previous
#include <cuda_runtime.h>
#include <cstdint>

// out[N,N] = diag(ics_mask - params * r_mask), N = 12288. Pure store-bound (604 MB).
// R9 finding: driver memset fills at the same ~6.8 TB/s as our kernel -> the
// ~84% of HBM spec is the chip's LTS fill ceiling (path-independent), not our
// store path. Fused kernel wins (no serialized diagonal pass). This round:
// fatter blocks (512 thr x 8 block-strided chunks, 64 KB/block) to cut block
// scheduling churn; stores stay fully coalesced, __stcs kept.

static constexpr unsigned N  = 12288u;
static constexpr unsigned N4 = (N * N) / 4u;     // 37,748,736 float4 stores
static constexpr unsigned THREADS = 512u;
static constexpr unsigned CHUNKS  = 8u;
static constexpr unsigned PER_BLOCK = THREADS * CHUNKS;   // 4096 float4s

__global__ void __launch_bounds__(THREADS) diag_fill_kernel(
    float4* __restrict__ out4,
    const float* __restrict__ params,
    const int*   __restrict__ r_mask,
    const int*   __restrict__ ics_mask)
{
    unsigned base = blockIdx.x * PER_BLOCK + threadIdx.x;

    #pragma unroll
    for (unsigned c = 0; c < CHUNKS; ++c) {
        unsigned f = base + c * THREADS;       // float4 index, < N4 exactly
        unsigned j = f * 4u;                   // first element index of window

        float4 v = make_float4(0.f, 0.f, 0.f, 0.f);

        // Diagonal indices d = i*(N+1); N+1 = 12289 > 4 -> at most one hit.
        unsigned i = (j + N) / (N + 1u);       // ceil(j/(N+1)) -> mul+shift
        unsigned d = i * (N + 1u);
        if (i < N && d < j + 4u) {
            float val = (float)ics_mask[i] - params[i] * (float)r_mask[i];
            unsigned off = d - j;
            if      (off == 0u) v.x = val;
            else if (off == 1u) v.y = val;
            else if (off == 2u) v.z = val;
            else                v.w = val;
        }

        __stcs(out4 + f, v);                   // st.global.cs.v4, coalesced
    }
}

extern "C" void kernel_launch(void* const* d_in, const int* in_sizes, int n_in,
                              void* d_out, int out_size)
{
    const float* params   = (const float*)d_in[0];
    const int*   r_mask   = (const int*)  d_in[1];
    const int*   ics_mask = (const int*)  d_in[2];
    float4*      out4     = (float4*)d_out;

    (void)in_sizes; (void)n_in; (void)out_size;

    const unsigned blocks = N4 / PER_BLOCK;    // 9216 — exact, no tail
    diag_fill_kernel<<<blocks, THREADS>>>(out4, params, r_mask, ics_mask);
}

// round 11
// speedup vs baseline: 1.0634x; 1.0116x over previous
#include <cuda_runtime.h>
#include <cstdint>

// out[N,N] = diag(ics_mask - params * r_mask), N = 12288. Pure store-bound (604 MB).
// FINAL: true fill rate is 604 MB / 81.3 us = 7.43 TB/s = 93% of HBM spec, and the
// driver memset control (R9) runs at the same rate -> chip fill ceiling reached,
// path-independent (LTS cap). This is the best-measured config (R8): 256 threads,
// 4 block-strided float4 chunks per thread (fully coalesced 16 KB per block),
// __stcs evict-first stores, exact grid with no tail.

static constexpr unsigned N  = 12288u;
static constexpr unsigned N4 = (N * N) / 4u;   // 37,748,736 float4 stores

__global__ void __launch_bounds__(256) diag_fill_kernel(
    float4* __restrict__ out4,
    const float* __restrict__ params,
    const int*   __restrict__ r_mask,
    const int*   __restrict__ ics_mask)
{
    // Block owns 4*256 = 1024 consecutive float4s. Chunk c: base + c*256.
    unsigned base = blockIdx.x * 1024u + threadIdx.x;

    #pragma unroll
    for (unsigned c = 0; c < 4u; ++c) {
        unsigned f = base + c * 256u;          // float4 index, < N4 exactly
        unsigned j = f * 4u;                   // first element index of window

        float4 v = make_float4(0.f, 0.f, 0.f, 0.f);

        // Diagonal indices d = i*(N+1); N+1 = 12289 > 4 -> at most one hit.
        unsigned i = (j + N) / (N + 1u);       // ceil(j/(N+1)) -> mul+shift
        unsigned d = i * (N + 1u);
        if (i < N && d < j + 4u) {
            float val = (float)ics_mask[i] - params[i] * (float)r_mask[i];
            unsigned off = d - j;
            if      (off == 0u) v.x = val;
            else if (off == 1u) v.y = val;
            else if (off == 2u) v.z = val;
            else                v.w = val;
        }

        __stcs(out4 + f, v);                   // st.global.cs.v4, coalesced
    }
}

extern "C" void kernel_launch(void* const* d_in, const int* in_sizes, int n_in,
                              void* d_out, int out_size)
{
    const float* params   = (const float*)d_in[0];
    const int*   r_mask   = (const int*)  d_in[1];
    const int*   ics_mask = (const int*)  d_in[2];
    float4*      out4     = (float4*)d_out;

    (void)in_sizes; (void)n_in; (void)out_size;

    const unsigned threads = 256;
    const unsigned blocks  = N4 / (threads * 4u);   // 36,864 — exact, no tail
    diag_fill_kernel<<<blocks, threads>>>(out4, params, r_mask, ics_mask);
}